// round 16
// baseline (speedup 1.0000x reference)
#include <cuda_runtime.h>
#include <cuda_bf16.h>
#include <cstdint>

// VectorQuantizer — bf16 HMMA GEMM (warp tile 64x32, BK=64, 2-stage) + refine/gather.
// inputs:  d_in[0] = inputs  [16,32,32,256] f32  (N=16384 rows, D=256)
//          d_in[1] = codebook [4096,256] f32     (K=4096)
// output:  d_out[0..N*D) = embeddings (straight-through), d_out[N*D] = loss

#define NR    16384
#define KCB   4096
#define DDIM  256
#define BM    128
#define BN    128
#define BK    64
#define NCH   (DDIM / BK)        // 4 k-chunks
#define ROWB  144u               // padded smem row bytes (128 data + 16 pad)
#define ARRB  (128u * ROWB)      // 18432 B per array
#define STGB  (2u * ARRB)        // 36864 B per stage (Ah, Bh)
#define NSTG  2
#define SMEM_DYN (NSTG * STGB)   // 73728 B
#define EPS   0.15f
#define CAP   128                // candidate slots per row

// ---------------- scratch (__device__ globals) -------------------------------
__device__ __nv_bfloat16 g_Ahi[NR * DDIM];
__device__ __nv_bfloat16 g_Bhi[KCB * DDIM];
__device__ unsigned long long g_cand[(size_t)NR * CAP];  // (f32bits(dred)<<32)|col
__device__ int            g_cand_cnt[NR];
__device__ unsigned int   g_rowmin_approx[NR];       // enc(d_red) global per row
__device__ unsigned int   g_class_min[KCB];
__device__ int            g_active[KCB];
__device__ float          g_mse;
__device__ float          g_xsq[NR];
__device__ float          g_csq[KCB];

// ---------------- helpers ----------------------------------------------------
__device__ __forceinline__ unsigned int enc_f(float f) {
    unsigned int u = __float_as_uint(f);
    return (u & 0x80000000u) ? ~u : (u | 0x80000000u);
}
__device__ __forceinline__ float dec_f(unsigned int e) {
    return (e & 0x80000000u) ? __uint_as_float(e ^ 0x80000000u)
                             : __uint_as_float(~e);
}
__device__ __forceinline__ uint32_t smem_u32(const void* p) {
    uint32_t a;
    asm("{ .reg .u64 t; cvta.to.shared.u64 t, %1; cvt.u32.u64 %0, t; }"
        : "=r"(a) : "l"(p));
    return a;
}
__device__ __forceinline__ void cp16(uint32_t dst, const void* src) {
    asm volatile("cp.async.cg.shared.global [%0], [%1], 16;"
                 :: "r"(dst), "l"(src) : "memory");
}
#define CP_COMMIT() asm volatile("cp.async.commit_group;" ::: "memory")
#define CP_WAIT0()  asm volatile("cp.async.wait_group 0;" ::: "memory")

__device__ __forceinline__ void ldsm4(uint32_t r[4], uint32_t addr) {
    asm volatile("ldmatrix.sync.aligned.m8n8.x4.shared.b16 {%0,%1,%2,%3}, [%4];"
                 : "=r"(r[0]), "=r"(r[1]), "=r"(r[2]), "=r"(r[3]) : "r"(addr));
}
__device__ __forceinline__ void mma_bf16(float c[4], const uint32_t a[4],
                                         uint32_t b0, uint32_t b1) {
    asm volatile(
        "mma.sync.aligned.m16n8k16.row.col.f32.bf16.bf16.f32 "
        "{%0,%1,%2,%3}, {%4,%5,%6,%7}, {%8,%9}, {%0,%1,%2,%3};"
        : "+f"(c[0]), "+f"(c[1]), "+f"(c[2]), "+f"(c[3])
        : "r"(a[0]), "r"(a[1]), "r"(a[2]), "r"(a[3]), "r"(b0), "r"(b1));
}

// ---------------- init --------------------------------------------------------
__global__ void vq_init_kernel() {
    int i = blockIdx.x * blockDim.x + threadIdx.x;
    if (i < NR) { g_rowmin_approx[i] = 0xFFFFFFFFu; g_cand_cnt[i] = 0; }
    if (i < KCB) { g_class_min[i] = 0xFFFFFFFFu; g_active[i] = 0; }
    if (i == 0) g_mse = 0.0f;
}

// ---------------- bf16 convert + squared norms -------------------------------
__global__ void vq_split_kernel(const float* __restrict__ src, int rows, int which) {
    int warp = threadIdx.x >> 5;
    int lane = threadIdx.x & 31;
    int row  = blockIdx.x * 8 + warp;
    if (row >= rows) return;
    __nv_bfloat16* hi = which ? g_Bhi : g_Ahi;
    float*         sq = which ? g_csq : g_xsq;
    const float4* s4 = reinterpret_cast<const float4*>(src + (size_t)row * DDIM);
    __nv_bfloat162* h2 = reinterpret_cast<__nv_bfloat162*>(hi + (size_t)row * DDIM);
    float acc = 0.0f;
#pragma unroll
    for (int j = lane; j < DDIM / 4; j += 32) {
        float4 v = s4[j];
        h2[2 * j]     = __nv_bfloat162(__float2bfloat16_rn(v.x), __float2bfloat16_rn(v.y));
        h2[2 * j + 1] = __nv_bfloat162(__float2bfloat16_rn(v.z), __float2bfloat16_rn(v.w));
        acc += v.x * v.x + v.y * v.y + v.z * v.z + v.w * v.w;
    }
#pragma unroll
    for (int o = 16; o; o >>= 1) acc += __shfl_xor_sync(0xFFFFFFFFu, acc, o);
    if (lane == 0) sq[row] = acc;
}

// ---------------- fused GEMM (bf16 HMMA, warp tile 64x32, 2 CTA/SM) -----------
// CTA: 128x128, 256 threads = 8 warps in 2(M)x4(N); warp tile 64x32.
// Per k16: 4 A-ldsm + 2 B-ldsm feed 16 MMAs (0.375 ldsm/MMA).
// Pipeline per chunk: WAIT0 -> sync -> LOAD(ch+1) -> compute(ch).
__global__ __launch_bounds__(256, 2)
void vq_gemm() {
    extern __shared__ char dynsm[];
    __shared__ unsigned int s_rowmin[BM];
    __shared__ unsigned int s_clsmin[BN];
    __shared__ float        s_xsq[BM];
    __shared__ float        s_csq[BN];

    const uint32_t sb = smem_u32(dynsm);
    const int tid  = threadIdx.x;
    const int lane = tid & 31;
    const int w    = tid >> 5;
    const int m_base = (w >> 2) * 64;     // 0 or 64
    const int n_base = (w & 3) * 32;
    const int tileM = blockIdx.y * BM;
    const int tileN = blockIdx.x * BN;

    if (tid < BM) {
        s_rowmin[tid] = 0xFFFFFFFFu;
        s_clsmin[tid] = 0xFFFFFFFFu;
        s_xsq[tid] = g_xsq[tileM + tid];
        s_csq[tid] = g_csq[tileN + tid];
    }

    const __nv_bfloat16* Ah = g_Ahi + (size_t)tileM * DDIM;
    const __nv_bfloat16* Bh = g_Bhi + (size_t)tileN * DDIM;

    float c[4][4][4];                     // [mt m16][nt n8][frag]
#pragma unroll
    for (int mt = 0; mt < 4; mt++)
#pragma unroll
        for (int nt = 0; nt < 4; nt++)
#pragma unroll
            for (int r = 0; r < 4; r++) c[mt][nt][r] = 0.0f;

    // loader: per chunk 2 arrays x 128 rows x 8 c16(16B) = 2048 cp16 / 256 thr
#define LOAD_CHUNK(stg, k0)                                              \
    do {                                                                 \
        uint32_t st_ = sb + (uint32_t)(stg) * STGB;                      \
        _Pragma("unroll")                                                \
        for (int j = 0; j < 4; j++) {                                    \
            int idx = tid + 256 * j;                                     \
            uint32_t off = (uint32_t)(idx >> 3) * ROWB +                 \
                           (uint32_t)(idx & 7) * 16u;                    \
            size_t src = (size_t)(idx >> 3) * DDIM + (idx & 7) * 8 + (k0); \
            cp16(st_ + off,        Ah + src);                            \
            cp16(st_ + ARRB + off, Bh + src);                            \
        }                                                                \
        CP_COMMIT();                                                     \
    } while (0)

    LOAD_CHUNK(0, 0);

    // ldmatrix lane addressing
    const uint32_t arow = (uint32_t)(m_base + (lane & 7) + 8 * ((lane >> 3) & 1));
    const uint32_t acol16 = 16u * (uint32_t)(lane >> 4);
    const uint32_t brow2 = (uint32_t)(n_base + ((lane >> 4) & 1) * 8 + (lane & 7));
    const uint32_t bcol2 = 16u * (uint32_t)((lane >> 3) & 1);

#pragma unroll
    for (int ch = 0; ch < NCH; ch++) {
        CP_WAIT0();
        __syncthreads();
        if (ch + 1 < NCH) LOAD_CHUNK((ch + 1) & 1, (ch + 1) * BK);

        const uint32_t st = sb + (uint32_t)(ch & 1) * STGB;
#pragma unroll
        for (int k16 = 0; k16 < 4; k16++) {
            uint32_t ah[4][4];
#pragma unroll
            for (int mt = 0; mt < 4; mt++) {
                uint32_t ra = (arow + 16u * mt) * ROWB + (uint32_t)(k16 * 32) + acol16;
                ldsm4(ah[mt], st + ra);
            }
            uint32_t bq[2][4];    // [pair p][m0..m3]; p=0 -> nt 0,1; p=1 -> nt 2,3
#pragma unroll
            for (int p = 0; p < 2; p++) {
                uint32_t rb = (brow2 + 16u * p) * ROWB + (uint32_t)(k16 * 32) + bcol2;
                ldsm4(bq[p], st + ARRB + rb);
            }
#pragma unroll
            for (int nt = 0; nt < 4; nt++) {
                uint32_t b0 = bq[nt >> 1][(nt & 1) * 2 + 0];
                uint32_t b1 = bq[nt >> 1][(nt & 1) * 2 + 1];
#pragma unroll
                for (int mt = 0; mt < 4; mt++)
                    mma_bf16(c[mt][nt], ah[mt], b0, b1);
            }
        }
    }

    // ---- epilogue: tile-local row-min + per-class min ----
    unsigned int cm[4][2];
#pragma unroll
    for (int nt = 0; nt < 4; nt++) { cm[nt][0] = 0xFFFFFFFFu; cm[nt][1] = 0xFFFFFFFFu; }

#pragma unroll
    for (int mt = 0; mt < 4; mt++)
#pragma unroll
        for (int h = 0; h < 2; h++) {
            const int rl = m_base + mt * 16 + (lane >> 2) + 8 * h;
            const float xq = s_xsq[rl];
            unsigned int best = 0xFFFFFFFFu;
#pragma unroll
            for (int nt = 0; nt < 4; nt++) {
                const int cl = n_base + nt * 8 + 2 * (lane & 3);
                float dr0 = fmaf(-2.0f, c[mt][nt][h * 2 + 0], s_csq[cl]);
                float dr1 = fmaf(-2.0f, c[mt][nt][h * 2 + 1], s_csq[cl + 1]);
                unsigned int e0 = enc_f(dr0);
                unsigned int e1 = enc_f(dr1);
                if (e0 < best) best = e0;
                if (e1 < best) best = e1;
                unsigned int f0 = enc_f(dr0 + xq);
                unsigned int f1 = enc_f(dr1 + xq);
                if (f0 < cm[nt][0]) cm[nt][0] = f0;
                if (f1 < cm[nt][1]) cm[nt][1] = f1;
            }
#pragma unroll
            for (int o = 1; o <= 2; o <<= 1) {
                unsigned int t = __shfl_xor_sync(0xFFFFFFFFu, best, o);
                if (t < best) best = t;
            }
            if ((lane & 3) == 0) atomicMin(&s_rowmin[rl], best);
        }

#pragma unroll
    for (int nt = 0; nt < 4; nt++)
#pragma unroll
        for (int b = 0; b < 2; b++) {
            unsigned int v = cm[nt][b];
#pragma unroll
            for (int o = 4; o <= 16; o <<= 1) {
                unsigned int t = __shfl_xor_sync(0xFFFFFFFFu, v, o);
                if (t < v) v = t;
            }
            if (lane < 4) atomicMin(&s_clsmin[n_base + nt * 8 + 2 * lane + b], v);
        }

    __syncthreads();
    if (tid < BM) {
        atomicMin(&g_rowmin_approx[tileM + tid], s_rowmin[tid]);
        atomicMin(&g_class_min[tileN + tid], s_clsmin[tid]);
    }

    // ---- candidate append: dred <= tile_min + EPS, quad-aggregated atomics ----
    // All __shfl_sync collectives execute unconditionally on every lane.
#pragma unroll
    for (int mt = 0; mt < 4; mt++)
#pragma unroll
        for (int h = 0; h < 2; h++) {
            const int rl = m_base + mt * 16 + (lane >> 2) + 8 * h;
            const int row = tileM + rl;
            const float thr = dec_f(s_rowmin[rl]) + EPS;
            unsigned int mask = 0;
#pragma unroll
            for (int nt = 0; nt < 4; nt++)
#pragma unroll
                for (int b = 0; b < 2; b++) {
                    const int cl = n_base + nt * 8 + 2 * (lane & 3) + b;
                    float dred = fmaf(-2.0f, c[mt][nt][h * 2 + b], s_csq[cl]);
                    if (dred <= thr) mask |= 1u << (nt * 2 + b);
                }
            int cnt = __popc(mask);
            int incl = cnt, t;
            t = __shfl_up_sync(0xFFFFFFFFu, incl, 1, 4); if ((lane & 3) >= 1) incl += t;
            t = __shfl_up_sync(0xFFFFFFFFu, incl, 2, 4); if ((lane & 3) >= 2) incl += t;
            int total = __shfl_sync(0xFFFFFFFFu, incl, 3, 4);
            int base = 0;
            if ((lane & 3) == 0 && total > 0)
                base = atomicAdd(&g_cand_cnt[row], total);
            base = __shfl_sync(0xFFFFFFFFu, base, 0, 4);   // unconditional
            int slot = base + (incl - cnt);
            if (mask) {
#pragma unroll
                for (int nt = 0; nt < 4; nt++)
#pragma unroll
                    for (int b = 0; b < 2; b++) {
                        if (mask & (1u << (nt * 2 + b))) {
                            const int cl = n_base + nt * 8 + 2 * (lane & 3) + b;
                            float dred = fmaf(-2.0f, c[mt][nt][h * 2 + b],
                                              s_csq[cl]);
                            if (slot < CAP)
                                g_cand[(size_t)row * CAP + slot] =
                                    ((unsigned long long)__float_as_uint(dred)
                                         << 32) |
                                    (unsigned int)(tileN + cl);
                            slot++;
                        }
                    }
            }
        }
}

// ---------------- fused refine + gather + MSE + active ------------------------
__global__ __launch_bounds__(256)
void vq_refine_gather(const float* __restrict__ xf, const float* __restrict__ cbf,
                      float* __restrict__ out) {
    const int warp = threadIdx.x >> 5;
    const int lane = threadIdx.x & 31;
    const int row  = blockIdx.x * 8 + warp;

    float s = 0.0f;
    if (row < NR) {
        const float thr = dec_f(g_rowmin_approx[row]) + EPS;
        const float4* xr = reinterpret_cast<const float4*>(xf + (size_t)row * DDIM);
        const float xq = g_xsq[row];
        const int cnt = g_cand_cnt[row];

        unsigned long long best = 0xFFFFFFFFFFFFFFFFull;
        if (cnt <= CAP) {
            const unsigned long long* cl = g_cand + (size_t)row * CAP;
            for (int i = lane; i < cnt; i += 32) {
                unsigned long long pc = cl[i];
                float dred = __uint_as_float((unsigned int)(pc >> 32));
                if (dred <= thr) {
                    const int col = (int)(pc & 0xFFFFFFFFull);
                    const float4* cr =
                        reinterpret_cast<const float4*>(cbf + (size_t)col * DDIM);
                    float dot = 0.0f;     // sequential k-order, one accumulator
#pragma unroll 8
                    for (int k = 0; k < DDIM / 4; k++) {
                        float4 a = xr[k];
                        float4 u = cr[k];
                        dot = fmaf(a.x, u.x, dot);
                        dot = fmaf(a.y, u.y, dot);
                        dot = fmaf(a.z, u.z, dot);
                        dot = fmaf(a.w, u.w, dot);
                    }
                    float dfull = fmaf(-2.0f, dot, xq + g_csq[col]);
                    unsigned long long p =
                        ((unsigned long long)enc_f(dfull) << 32) |
                        (unsigned int)col;
                    if (p < best) best = p;
                }
            }
        } else {
            // overflow fallback (deterministic): full exact scan of the row.
            for (int col = lane; col < KCB; col += 32) {
                const float4* cr =
                    reinterpret_cast<const float4*>(cbf + (size_t)col * DDIM);
                float dot = 0.0f;
#pragma unroll 8
                for (int k = 0; k < DDIM / 4; k++) {
                    float4 a = xr[k];
                    float4 u = cr[k];
                    dot = fmaf(a.x, u.x, dot);
                    dot = fmaf(a.y, u.y, dot);
                    dot = fmaf(a.z, u.z, dot);
                    dot = fmaf(a.w, u.w, dot);
                }
                float dfull = fmaf(-2.0f, dot, xq + g_csq[col]);
                unsigned long long p =
                    ((unsigned long long)enc_f(dfull) << 32) | (unsigned int)col;
                if (p < best) best = p;
            }
        }
#pragma unroll
        for (int o = 16; o; o >>= 1) {
            unsigned long long t = __shfl_xor_sync(0xFFFFFFFFu, best, o);
            if (t < best) best = t;
        }
        const unsigned int tok = (unsigned int)(best & 0xFFFFFFFFull);
        if (lane == 0) g_active[tok] = 1;

        const float4* cp = reinterpret_cast<const float4*>(cbf + (size_t)tok * DDIM);
        float4*       op = reinterpret_cast<float4*>(out + (size_t)row * DDIM);
#pragma unroll
        for (int j2 = lane; j2 < DDIM / 4; j2 += 32) {
            float4 cc = cp[j2];
            float4 v2 = xr[j2];
            op[j2] = cc;
            float dx = cc.x - v2.x, dy = cc.y - v2.y;
            float dz = cc.z - v2.z, dw = cc.w - v2.w;
            s += dx * dx + dy * dy + dz * dz + dw * dw;
        }
    }
#pragma unroll
    for (int o = 16; o; o >>= 1) s += __shfl_xor_sync(0xFFFFFFFFu, s, o);
    __shared__ float ws[8];
    if (lane == 0) ws[warp] = s;
    __syncthreads();
    if (threadIdx.x == 0) {
        float t = 0.0f;
#pragma unroll
        for (int w2 = 0; w2 < 8; w2++) t += ws[w2];
        atomicAdd(&g_mse, t);
    }
}

// ---------------- finalize loss ----------------------------------------------
__global__ void vq_finalize_kernel(float* __restrict__ out, int nd) {
    __shared__ float sh[256];
    float s = 0.0f;
    for (int k = threadIdx.x; k < KCB; k += 256) {
        if (g_active[k] == 0) s += dec_f(g_class_min[k]);
    }
    sh[threadIdx.x] = s;
    __syncthreads();
    for (int o = 128; o; o >>= 1) {
        if (threadIdx.x < o) sh[threadIdx.x] += sh[threadIdx.x + o];
        __syncthreads();
    }
    if (threadIdx.x == 0) {
        float mse = g_mse / (float)((size_t)NR * DDIM);
        float ent = sh[0] / (float)KCB;
        out[nd] = 1.25f * mse + 0.02f * ent;
    }
}

// ---------------- launcher ----------------------------------------------------
extern "C" void kernel_launch(void* const* d_in, const int* in_sizes, int n_in,
                              void* d_out, int out_size) {
    const float* x  = (const float*)d_in[0];
    const float* cb = (const float*)d_in[1];
    float* out = (float*)d_out;

    cudaFuncSetAttribute(vq_gemm,
                         cudaFuncAttributeMaxDynamicSharedMemorySize, SMEM_DYN);

    vq_init_kernel<<<(NR + 255) / 256, 256>>>();
    vq_split_kernel<<<NR / 8, 256>>>(x, NR, 0);
    vq_split_kernel<<<KCB / 8, 256>>>(cb, KCB, 1);

    dim3 grid(KCB / BN, NR / BM);   // (32, 128) = 4096 CTAs
    vq_gemm<<<grid, 256, SMEM_DYN>>>();

    vq_refine_gather<<<NR / 8, 256>>>(x, cb, out);
    vq_finalize_kernel<<<1, 256>>>(out, NR * DDIM);
}

// round 17
// speedup vs baseline: 1.1209x; 1.1209x over previous
#include <cuda_runtime.h>
#include <cuda_bf16.h>
#include <cstdint>

// VectorQuantizer — bf16 HMMA GEMM (r15 config) + fused prep and refine/finalize.
// inputs:  d_in[0] = inputs  [16,32,32,256] f32  (N=16384 rows, D=256)
//          d_in[1] = codebook [4096,256] f32     (K=4096)
// output:  d_out[0..N*D) = embeddings (straight-through), d_out[N*D] = loss

#define NR    16384
#define KCB   4096
#define DDIM  256
#define BM    128
#define BN    128
#define BK    64
#define NCH   (DDIM / BK)        // 4 k-chunks
#define ROWB  144u               // padded smem row bytes (128 data + 16 pad)
#define ARRB  (128u * ROWB)      // 18432 B per array
#define STGB  (2u * ARRB)        // 36864 B per stage (Ah, Bh)
#define NSTG  2
#define SMEM_DYN (NSTG * STGB)   // 73728 B
#define EPS   0.15f
#define CAP   128                // candidate slots per row

// ---------------- scratch (__device__ globals) -------------------------------
__device__ __nv_bfloat16 g_Ahi[NR * DDIM];
__device__ __nv_bfloat16 g_Bhi[KCB * DDIM];
__device__ unsigned long long g_cand[(size_t)NR * CAP];  // (f32bits(dred)<<32)|col
__device__ int            g_cand_cnt[NR];
__device__ unsigned int   g_rowmin_approx[NR];       // enc(d_red) global per row
__device__ unsigned int   g_class_min[KCB];
__device__ int            g_active[KCB];
__device__ float          g_mse;
__device__ int            g_done;
__device__ float          g_xsq[NR];
__device__ float          g_csq[KCB];

// ---------------- helpers ----------------------------------------------------
__device__ __forceinline__ unsigned int enc_f(float f) {
    unsigned int u = __float_as_uint(f);
    return (u & 0x80000000u) ? ~u : (u | 0x80000000u);
}
__device__ __forceinline__ float dec_f(unsigned int e) {
    return (e & 0x80000000u) ? __uint_as_float(e ^ 0x80000000u)
                             : __uint_as_float(~e);
}
__device__ __forceinline__ uint32_t smem_u32(const void* p) {
    uint32_t a;
    asm("{ .reg .u64 t; cvta.to.shared.u64 t, %1; cvt.u32.u64 %0, t; }"
        : "=r"(a) : "l"(p));
    return a;
}
__device__ __forceinline__ void cp16(uint32_t dst, const void* src) {
    asm volatile("cp.async.cg.shared.global [%0], [%1], 16;"
                 :: "r"(dst), "l"(src) : "memory");
}
#define CP_COMMIT() asm volatile("cp.async.commit_group;" ::: "memory")
#define CP_WAIT0()  asm volatile("cp.async.wait_group 0;" ::: "memory")

__device__ __forceinline__ void ldsm4(uint32_t r[4], uint32_t addr) {
    asm volatile("ldmatrix.sync.aligned.m8n8.x4.shared.b16 {%0,%1,%2,%3}, [%4];"
                 : "=r"(r[0]), "=r"(r[1]), "=r"(r[2]), "=r"(r[3]) : "r"(addr));
}
__device__ __forceinline__ void mma_bf16(float c[4], const uint32_t a[4],
                                         uint32_t b0, uint32_t b1) {
    asm volatile(
        "mma.sync.aligned.m16n8k16.row.col.f32.bf16.bf16.f32 "
        "{%0,%1,%2,%3}, {%4,%5,%6,%7}, {%8,%9}, {%0,%1,%2,%3};"
        : "+f"(c[0]), "+f"(c[1]), "+f"(c[2]), "+f"(c[3])
        : "r"(a[0]), "r"(a[1]), "r"(a[2]), "r"(a[3]), "r"(b0), "r"(b1));
}

// ---------------- fused prep: init + bf16 split + squared norms ---------------
// grid = NR/8 + KCB/8 blocks of 256. Blocks [0, NR/8) convert inputs;
// the rest convert the codebook. Init work is strided across all threads.
__global__ void vq_prep(const float* __restrict__ x, const float* __restrict__ cb) {
    const int t = blockIdx.x * blockDim.x + threadIdx.x;
    if (t < NR) { g_rowmin_approx[t] = 0xFFFFFFFFu; g_cand_cnt[t] = 0; }
    if (t < KCB) { g_class_min[t] = 0xFFFFFFFFu; g_active[t] = 0; }
    if (t == 0) { g_mse = 0.0f; g_done = 0; }

    const int warp = threadIdx.x >> 5;
    const int lane = threadIdx.x & 31;
    const int which = (blockIdx.x >= NR / 8) ? 1 : 0;
    const int row = which ? (blockIdx.x - NR / 8) * 8 + warp
                          : blockIdx.x * 8 + warp;
    const int rows = which ? KCB : NR;
    if (row >= rows) return;

    const float* src = which ? cb : x;
    __nv_bfloat16* hi = which ? g_Bhi : g_Ahi;
    float*         sq = which ? g_csq : g_xsq;
    const float4* s4 = reinterpret_cast<const float4*>(src + (size_t)row * DDIM);
    __nv_bfloat162* h2 = reinterpret_cast<__nv_bfloat162*>(hi + (size_t)row * DDIM);
    float acc = 0.0f;
#pragma unroll
    for (int j = lane; j < DDIM / 4; j += 32) {
        float4 v = s4[j];
        h2[2 * j]     = __nv_bfloat162(__float2bfloat16_rn(v.x), __float2bfloat16_rn(v.y));
        h2[2 * j + 1] = __nv_bfloat162(__float2bfloat16_rn(v.z), __float2bfloat16_rn(v.w));
        acc += v.x * v.x + v.y * v.y + v.z * v.z + v.w * v.w;
    }
#pragma unroll
    for (int o = 16; o; o >>= 1) acc += __shfl_xor_sync(0xFFFFFFFFu, acc, o);
    if (lane == 0) sq[row] = acc;
}

// ---------------- fused GEMM (bf16 HMMA, BK=64, 2-stage, 2 CTA/SM) ------------
// CTA: 128x128, 512 threads = 16 warps in 4(M)x4(N); warp tile 32x32.
// (Byte-identical mainloop/epilogue to the round-15 passing kernel.)
__global__ __launch_bounds__(512, 2)
void vq_gemm() {
    extern __shared__ char dynsm[];
    __shared__ unsigned int s_rowmin[BM];
    __shared__ unsigned int s_clsmin[BN];
    __shared__ float        s_xsq[BM];
    __shared__ float        s_csq[BN];

    const uint32_t sb = smem_u32(dynsm);
    const int tid  = threadIdx.x;
    const int lane = tid & 31;
    const int w    = tid >> 5;
    const int m_base = (w >> 2) * 32;
    const int n_base = (w & 3) * 32;
    const int tileM = blockIdx.y * BM;
    const int tileN = blockIdx.x * BN;

    if (tid < BM) {
        s_rowmin[tid] = 0xFFFFFFFFu;
        s_clsmin[tid] = 0xFFFFFFFFu;
        s_xsq[tid] = g_xsq[tileM + tid];
        s_csq[tid] = g_csq[tileN + tid];
    }

    const __nv_bfloat16* Ah = g_Ahi + (size_t)tileM * DDIM;
    const __nv_bfloat16* Bh = g_Bhi + (size_t)tileN * DDIM;

    float c[2][4][4];
#pragma unroll
    for (int mt = 0; mt < 2; mt++)
#pragma unroll
        for (int nt = 0; nt < 4; nt++)
#pragma unroll
            for (int r = 0; r < 4; r++) c[mt][nt][r] = 0.0f;

    const int lrow = tid >> 3;          // 0..63
    const int lc16 = tid & 7;           // 0..7
    const uint32_t ldst = (uint32_t)lrow * ROWB + (uint32_t)lc16 * 16u;
    const size_t lsrc = (size_t)lrow * DDIM + lc16 * 8;

#define LOAD_CHUNK(stg, k0)                                              \
    do {                                                                 \
        uint32_t st_ = sb + (uint32_t)(stg) * STGB;                      \
        cp16(st_ + ldst,                      Ah + lsrc + (k0));         \
        cp16(st_ + 64u * ROWB + ldst,         Ah + 64 * DDIM + lsrc + (k0)); \
        cp16(st_ + ARRB + ldst,               Bh + lsrc + (k0));         \
        cp16(st_ + ARRB + 64u * ROWB + ldst,  Bh + 64 * DDIM + lsrc + (k0)); \
        CP_COMMIT();                                                     \
    } while (0)

    LOAD_CHUNK(0, 0);

    const uint32_t arow = (uint32_t)(m_base + (lane & 7) + 8 * ((lane >> 3) & 1));
    const uint32_t acol16 = 16u * (uint32_t)(lane >> 4);
    const uint32_t brow2 = (uint32_t)(n_base + ((lane >> 4) & 1) * 8 + (lane & 7));
    const uint32_t bcol2 = 16u * (uint32_t)((lane >> 3) & 1);

#pragma unroll
    for (int ch = 0; ch < NCH; ch++) {
        CP_WAIT0();
        __syncthreads();
        if (ch + 1 < NCH) LOAD_CHUNK((ch + 1) & 1, (ch + 1) * BK);

        const uint32_t st = sb + (uint32_t)(ch & 1) * STGB;
#pragma unroll
        for (int k16 = 0; k16 < 4; k16++) {
            uint32_t ah[2][4];
#pragma unroll
            for (int mt = 0; mt < 2; mt++) {
                uint32_t ra = (arow + 16u * mt) * ROWB + (uint32_t)(k16 * 32) + acol16;
                ldsm4(ah[mt], st + ra);
            }
            uint32_t bq[2][4];
#pragma unroll
            for (int p = 0; p < 2; p++) {
                uint32_t rb = (brow2 + 16u * p) * ROWB + (uint32_t)(k16 * 32) + bcol2;
                ldsm4(bq[p], st + ARRB + rb);
            }
#pragma unroll
            for (int nt = 0; nt < 4; nt++) {
                uint32_t b0 = bq[nt >> 1][(nt & 1) * 2 + 0];
                uint32_t b1 = bq[nt >> 1][(nt & 1) * 2 + 1];
#pragma unroll
                for (int mt = 0; mt < 2; mt++)
                    mma_bf16(c[mt][nt], ah[mt], b0, b1);
            }
        }
    }

    // ---- epilogue: tile-local row-min + per-class min ----
    unsigned int cm[4][2];
#pragma unroll
    for (int nt = 0; nt < 4; nt++) { cm[nt][0] = 0xFFFFFFFFu; cm[nt][1] = 0xFFFFFFFFu; }

#pragma unroll
    for (int mt = 0; mt < 2; mt++)
#pragma unroll
        for (int h = 0; h < 2; h++) {
            const int rl = m_base + mt * 16 + (lane >> 2) + 8 * h;
            const float xq = s_xsq[rl];
            unsigned int best = 0xFFFFFFFFu;
#pragma unroll
            for (int nt = 0; nt < 4; nt++) {
                const int cl = n_base + nt * 8 + 2 * (lane & 3);
                float dr0 = fmaf(-2.0f, c[mt][nt][h * 2 + 0], s_csq[cl]);
                float dr1 = fmaf(-2.0f, c[mt][nt][h * 2 + 1], s_csq[cl + 1]);
                unsigned int e0 = enc_f(dr0);
                unsigned int e1 = enc_f(dr1);
                if (e0 < best) best = e0;
                if (e1 < best) best = e1;
                unsigned int f0 = enc_f(dr0 + xq);
                unsigned int f1 = enc_f(dr1 + xq);
                if (f0 < cm[nt][0]) cm[nt][0] = f0;
                if (f1 < cm[nt][1]) cm[nt][1] = f1;
            }
#pragma unroll
            for (int o = 1; o <= 2; o <<= 1) {
                unsigned int t = __shfl_xor_sync(0xFFFFFFFFu, best, o);
                if (t < best) best = t;
            }
            if ((lane & 3) == 0) atomicMin(&s_rowmin[rl], best);
        }

#pragma unroll
    for (int nt = 0; nt < 4; nt++)
#pragma unroll
        for (int b = 0; b < 2; b++) {
            unsigned int v = cm[nt][b];
#pragma unroll
            for (int o = 4; o <= 16; o <<= 1) {
                unsigned int t = __shfl_xor_sync(0xFFFFFFFFu, v, o);
                if (t < v) v = t;
            }
            if (lane < 4) atomicMin(&s_clsmin[n_base + nt * 8 + 2 * lane + b], v);
        }

    __syncthreads();
    if (tid < BM) {
        atomicMin(&g_rowmin_approx[tileM + tid], s_rowmin[tid]);
        atomicMin(&g_class_min[tileN + tid], s_clsmin[tid]);
    }

    // ---- candidate append: dred <= tile_min + EPS, quad-aggregated atomics ----
#pragma unroll
    for (int mt = 0; mt < 2; mt++)
#pragma unroll
        for (int h = 0; h < 2; h++) {
            const int rl = m_base + mt * 16 + (lane >> 2) + 8 * h;
            const int row = tileM + rl;
            const float thr = dec_f(s_rowmin[rl]) + EPS;
            unsigned int mask = 0;
#pragma unroll
            for (int nt = 0; nt < 4; nt++)
#pragma unroll
                for (int b = 0; b < 2; b++) {
                    const int cl = n_base + nt * 8 + 2 * (lane & 3) + b;
                    float dred = fmaf(-2.0f, c[mt][nt][h * 2 + b], s_csq[cl]);
                    if (dred <= thr) mask |= 1u << (nt * 2 + b);
                }
            int cnt = __popc(mask);
            int incl = cnt, t;
            t = __shfl_up_sync(0xFFFFFFFFu, incl, 1, 4); if ((lane & 3) >= 1) incl += t;
            t = __shfl_up_sync(0xFFFFFFFFu, incl, 2, 4); if ((lane & 3) >= 2) incl += t;
            int total = __shfl_sync(0xFFFFFFFFu, incl, 3, 4);
            int base = 0;
            if ((lane & 3) == 0 && total > 0)
                base = atomicAdd(&g_cand_cnt[row], total);
            base = __shfl_sync(0xFFFFFFFFu, base, 0, 4);   // unconditional
            int slot = base + (incl - cnt);
            if (mask) {
#pragma unroll
                for (int nt = 0; nt < 4; nt++)
#pragma unroll
                    for (int b = 0; b < 2; b++) {
                        if (mask & (1u << (nt * 2 + b))) {
                            const int cl = n_base + nt * 8 + 2 * (lane & 3) + b;
                            float dred = fmaf(-2.0f, c[mt][nt][h * 2 + b],
                                              s_csq[cl]);
                            if (slot < CAP)
                                g_cand[(size_t)row * CAP + slot] =
                                    ((unsigned long long)__float_as_uint(dred)
                                         << 32) |
                                    (unsigned int)(tileN + cl);
                            slot++;
                        }
                    }
            }
        }
}

// ---------------- fused refine + gather + MSE + active + finalize -------------
// 1 warp per row; last block (atomic done-counter) computes the loss scalar.
__global__ __launch_bounds__(256)
void vq_refine_gather(const float* __restrict__ xf, const float* __restrict__ cbf,
                      float* __restrict__ out, int nblocks) {
    const int warp = threadIdx.x >> 5;
    const int lane = threadIdx.x & 31;
    const int row  = blockIdx.x * 8 + warp;

    float s = 0.0f;
    if (row < NR) {
        const float thr = dec_f(g_rowmin_approx[row]) + EPS;
        const float4* xr = reinterpret_cast<const float4*>(xf + (size_t)row * DDIM);
        const float xq = g_xsq[row];
        const int cnt = g_cand_cnt[row];

        unsigned long long best = 0xFFFFFFFFFFFFFFFFull;
        if (cnt <= CAP) {
            const unsigned long long* cl = g_cand + (size_t)row * CAP;
            for (int i = lane; i < cnt; i += 32) {
                unsigned long long pc = cl[i];
                float dred = __uint_as_float((unsigned int)(pc >> 32));
                if (dred <= thr) {
                    const int col = (int)(pc & 0xFFFFFFFFull);
                    const float4* cr =
                        reinterpret_cast<const float4*>(cbf + (size_t)col * DDIM);
                    float dot = 0.0f;     // sequential k-order, one accumulator
#pragma unroll 8
                    for (int k = 0; k < DDIM / 4; k++) {
                        float4 a = xr[k];
                        float4 u = cr[k];
                        dot = fmaf(a.x, u.x, dot);
                        dot = fmaf(a.y, u.y, dot);
                        dot = fmaf(a.z, u.z, dot);
                        dot = fmaf(a.w, u.w, dot);
                    }
                    float dfull = fmaf(-2.0f, dot, xq + g_csq[col]);
                    unsigned long long p =
                        ((unsigned long long)enc_f(dfull) << 32) |
                        (unsigned int)col;
                    if (p < best) best = p;
                }
            }
        } else {
            // overflow fallback (deterministic): full exact scan of the row.
            for (int col = lane; col < KCB; col += 32) {
                const float4* cr =
                    reinterpret_cast<const float4*>(cbf + (size_t)col * DDIM);
                float dot = 0.0f;
#pragma unroll 8
                for (int k = 0; k < DDIM / 4; k++) {
                    float4 a = xr[k];
                    float4 u = cr[k];
                    dot = fmaf(a.x, u.x, dot);
                    dot = fmaf(a.y, u.y, dot);
                    dot = fmaf(a.z, u.z, dot);
                    dot = fmaf(a.w, u.w, dot);
                }
                float dfull = fmaf(-2.0f, dot, xq + g_csq[col]);
                unsigned long long p =
                    ((unsigned long long)enc_f(dfull) << 32) | (unsigned int)col;
                if (p < best) best = p;
            }
        }
#pragma unroll
        for (int o = 16; o; o >>= 1) {
            unsigned long long t = __shfl_xor_sync(0xFFFFFFFFu, best, o);
            if (t < best) best = t;
        }
        const unsigned int tok = (unsigned int)(best & 0xFFFFFFFFull);
        if (lane == 0) g_active[tok] = 1;

        const float4* cp = reinterpret_cast<const float4*>(cbf + (size_t)tok * DDIM);
        float4*       op = reinterpret_cast<float4*>(out + (size_t)row * DDIM);
#pragma unroll
        for (int j2 = lane; j2 < DDIM / 4; j2 += 32) {
            float4 cc = cp[j2];
            float4 v2 = xr[j2];
            op[j2] = cc;
            float dx = cc.x - v2.x, dy = cc.y - v2.y;
            float dz = cc.z - v2.z, dw = cc.w - v2.w;
            s += dx * dx + dy * dy + dz * dz + dw * dw;
        }
    }
#pragma unroll
    for (int o = 16; o; o >>= 1) s += __shfl_xor_sync(0xFFFFFFFFu, s, o);
    __shared__ float ws[8];
    __shared__ int   s_last;
    if (lane == 0) ws[warp] = s;
    __syncthreads();
    if (threadIdx.x == 0) {
        float t = 0.0f;
#pragma unroll
        for (int w2 = 0; w2 < 8; w2++) t += ws[w2];
        atomicAdd(&g_mse, t);
        __threadfence();
        int p = atomicAdd(&g_done, 1);
        s_last = (p == nblocks - 1);
    }
    __syncthreads();

    if (s_last) {
        // finalize: entropy term over never-selected classes + loss write
        __shared__ float sh[256];
        float e = 0.0f;
        for (int k = threadIdx.x; k < KCB; k += 256) {
            if (g_active[k] == 0) e += dec_f(g_class_min[k]);
        }
        sh[threadIdx.x] = e;
        __syncthreads();
        for (int o = 128; o; o >>= 1) {
            if (threadIdx.x < o) sh[threadIdx.x] += sh[threadIdx.x + o];
            __syncthreads();
        }
        if (threadIdx.x == 0) {
            float mse = g_mse / (float)((size_t)NR * DDIM);
            float ent = sh[0] / (float)KCB;
            out[NR * DDIM] = 1.25f * mse + 0.02f * ent;
        }
    }
}

// ---------------- launcher ----------------------------------------------------
extern "C" void kernel_launch(void* const* d_in, const int* in_sizes, int n_in,
                              void* d_out, int out_size) {
    const float* x  = (const float*)d_in[0];
    const float* cb = (const float*)d_in[1];
    float* out = (float*)d_out;

    cudaFuncSetAttribute(vq_gemm,
                         cudaFuncAttributeMaxDynamicSharedMemorySize, SMEM_DYN);

    vq_prep<<<NR / 8 + KCB / 8, 256>>>(x, cb);

    dim3 grid(KCB / BN, NR / BM);   // (32, 128) = 4096 CTAs
    vq_gemm<<<grid, 512, SMEM_DYN>>>();

    vq_refine_gather<<<NR / 8, 256>>>(x, cb, out, NR / 8);
}